// round 14
// baseline (speedup 1.0000x reference)
#include <cuda_runtime.h>
#include <cstdint>

#define BSZ  16
#define NSEQ 1024
#define EMB  768
#define NH   12
#define HD   64
#define MTOT (BSZ*NSEQ)   // 16384
#define SCALE 0.125f      // 64^-0.5
#define QSCALE (0.125f * 1.44269504088896340736f)   // SCALE * log2(e)
#define KT   96           // k-chunks of 8 (768/8)
#define MT   1024         // m-tiles of 16 (16384/16)
#define NT   96           // n-tiles of 8 (768/8)
#define WSZ  (NT*KT*32)   // uint2 elements per packed W
#define NHEADS (BSZ*NH)   // 192

// ---------------- scratch (device globals; allocation-free) ----------------
__device__ uint4 g_Axf[MT*KT*32];            // packed x      A-fragments (tf32)
__device__ uint4 g_Aof[MT*KT*32];            // packed attn-O A-fragments (tf32)
__device__ uint2 g_Wf[4][WSZ];               // packed Wq,Wk,Wv,Wo B-fragments
__device__ uint4 g_Qf[NHEADS*64*8*32];       // Q A-frags [head][mt(64)][kc(8)][lane]
__device__ uint4 g_Kf4[NHEADS*128*4*32];     // K B-frags kc-paired [head][nt(128)][p(4)][lane]
__device__ uint4 g_Vf4[NHEADS*16*4*8*32];    // V B-frags kc-paired [head][chunk(16)][p(4)][g(8)][lane]

// ---------------- helpers ----------------
__device__ __forceinline__ uint32_t f2tf32(float v) {
    uint32_t u;
    asm("cvt.rna.tf32.f32 %0, %1;" : "=r"(u) : "f"(v));
    return u;
}
__device__ __forceinline__ float ex2f(float v) {
    float r;
    asm("ex2.approx.f32 %0, %1;" : "=f"(r) : "f"(v));
    return r;
}
__device__ __forceinline__ uint32_t s2u(const void* p) {
    uint32_t a;
    asm("{ .reg .u64 t; cvta.to.shared.u64 t, %1; cvt.u32.u64 %0, t; }" : "=r"(a) : "l"(p));
    return a;
}
__device__ __forceinline__ void mma_tf32(float* c, const uint32_t* a, const uint32_t* b) {
    asm volatile(
        "mma.sync.aligned.m16n8k8.row.col.f32.tf32.tf32.f32 "
        "{%0,%1,%2,%3}, {%4,%5,%6,%7}, {%8,%9}, {%0,%1,%2,%3};"
        : "+f"(c[0]), "+f"(c[1]), "+f"(c[2]), "+f"(c[3])
        : "r"(a[0]), "r"(a[1]), "r"(a[2]), "r"(a[3]), "r"(b[0]), "r"(b[1]));
}

// ---------------------------------------------------------------------------
// pack_A ; pack_B4 (all four W in one launch, grid.y selects matrix)
// ---------------------------------------------------------------------------
__global__ __launch_bounds__(256)
void pack_A(const float* __restrict__ A, uint4* __restrict__ out)
{
    const int t = blockIdx.x * 256 + threadIdx.x;
    const int lane = t & 31, f = t >> 5;
    const int mt = f / KT, kc = f % KT;
    const float* base = A + (size_t)(mt * 16 + (lane >> 2)) * EMB + kc * 8 + (lane & 3);
    uint4 o;
    o.x = f2tf32(base[0]);
    o.y = f2tf32(base[8 * EMB]);
    o.z = f2tf32(base[4]);
    o.w = f2tf32(base[8 * EMB + 4]);
    out[t] = o;
}

__global__ __launch_bounds__(256)
void pack_B4(const float* __restrict__ W0, const float* __restrict__ W1,
             const float* __restrict__ W2, const float* __restrict__ W3,
             uint2* __restrict__ out)
{
    const float* W = (blockIdx.y == 0) ? W0 : (blockIdx.y == 1) ? W1
                   : (blockIdx.y == 2) ? W2 : W3;
    const int t = blockIdx.x * 256 + threadIdx.x;
    const int lane = t & 31, f = t >> 5;
    const int nt = f / KT, kc = f % KT;
    const float* base = W + (size_t)(nt * 8 + (lane >> 2)) * EMB + kc * 8 + (lane & 3);
    uint2 o;
    o.x = f2tf32(base[0]);
    o.y = f2tf32(base[4]);
    out[(size_t)blockIdx.y * WSZ + t] = o;
}

// ---------------------------------------------------------------------------
// GEMM mainloop (unchanged: BM=128, BN=128, 8 warps 4x2, distance-1 prefetch)
// ---------------------------------------------------------------------------
__device__ __forceinline__ void gemm_mainloop(
    const uint4* __restrict__ pa0, const uint4* __restrict__ pa1,
    const uint2* __restrict__ pb, float acc[2][8][4])
{
    #pragma unroll
    for (int t = 0; t < 2; t++)
        #pragma unroll
        for (int j = 0; j < 8; j++)
            #pragma unroll
            for (int e = 0; e < 4; e++) acc[t][j][e] = 0.f;

    uint4 a0 = pa0[0], a1 = pa1[0];
    uint2 b[8];
    #pragma unroll
    for (int j = 0; j < 8; j++) b[j] = pb[j * KT * 32];

    #pragma unroll 2
    for (int kc = 0; kc < KT; kc++) {
        const uint4 ca0 = a0, ca1 = a1;
        uint2 cb[8];
        #pragma unroll
        for (int j = 0; j < 8; j++) cb[j] = b[j];
        if (kc + 1 < KT) {
            a0 = pa0[(kc + 1) * 32];
            a1 = pa1[(kc + 1) * 32];
            #pragma unroll
            for (int j = 0; j < 8; j++) b[j] = pb[(j * KT + kc + 1) * 32];
        }
        #pragma unroll
        for (int j = 0; j < 8; j++) {
            mma_tf32(acc[0][j], (const uint32_t*)&ca0.x, (const uint32_t*)&cb[j].x);
            mma_tf32(acc[1][j], (const uint32_t*)&ca1.x, (const uint32_t*)&cb[j].x);
        }
    }
}

// ---------------------------------------------------------------------------
// Fused QKV GEMM: blockIdx.z = 0:Q(A-frags, QSCALE) 1:K(kc-paired B-frags)
//                 2:V(kc-paired transposed B-frags)
// ---------------------------------------------------------------------------
__global__ __launch_bounds__(256, 2)
void gemm_qkv(const uint4* __restrict__ Af, const uint2* __restrict__ Wf,
              const float* __restrict__ bq, const float* __restrict__ bk,
              const float* __restrict__ bv,
              uint4* __restrict__ Qf, uint2* __restrict__ Kf2, uint4* __restrict__ Vf4)
{
    const int tid = threadIdx.x, warp = tid >> 5, lane = tid & 31;
    const int wm = warp & 3, wn = warp >> 2;
    const int mt0 = blockIdx.y * 8 + wm * 2;
    const int ntb = blockIdx.x * 16 + wn * 8;
    const int mode = blockIdx.z;

    const uint2* Bf = Wf + (size_t)mode * WSZ;
    const float* bias = (mode == 0) ? bq : (mode == 1) ? bk : bv;

    const uint4* pa0 = Af + (size_t)(mt0 + 0) * KT * 32 + lane;
    const uint4* pa1 = Af + (size_t)(mt0 + 1) * KT * 32 + lane;
    const uint2* pb  = Bf + (size_t)ntb * KT * 32 + lane;

    float acc[2][8][4];
    gemm_mainloop(pa0, pa1, pb, acc);

    const int cq = 2 * (lane & 3);
    const int srcA = (lane & ~3) | ((lane & 3) >> 1);
    const int srcB = srcA | 2;
    const bool odd = (lane & 1);

    #pragma unroll
    for (int t = 0; t < 2; t++) {
        const int mt_g = mt0 + t;
        #pragma unroll
        for (int j = 0; j < 8; j++) {
            const int col = (ntb + j) * 8 + cq;
            float2 bvv = *(const float2*)(bias + col);
            float v0 = acc[t][j][0] + bvv.x, v1 = acc[t][j][1] + bvv.y;
            float v2 = acc[t][j][2] + bvv.x, v3 = acc[t][j][3] + bvv.y;

            const int bb = mt_g >> 6;           // batch
            const int st = mt_g & 63;           // seq tile within batch
            const int col0 = (ntb + j) * 8;
            const int h  = col0 >> 6;           // head 0..11
            const int sub = (col0 & 63) >> 3;   // d-tile 0..7
            const int headg = bb * NH + h;

            if (mode == 0) {
                uint32_t c0 = f2tf32(v0 * QSCALE), c1 = f2tf32(v1 * QSCALE);
                uint32_t c2 = f2tf32(v2 * QSCALE), c3 = f2tf32(v3 * QSCALE);
                uint32_t a0a = __shfl_sync(0xffffffffu, c0, srcA);
                uint32_t a0b = __shfl_sync(0xffffffffu, c1, srcA);
                uint32_t a1a = __shfl_sync(0xffffffffu, c2, srcA);
                uint32_t a1b = __shfl_sync(0xffffffffu, c3, srcA);
                uint32_t a2a = __shfl_sync(0xffffffffu, c0, srcB);
                uint32_t a2b = __shfl_sync(0xffffffffu, c1, srcB);
                uint32_t a3a = __shfl_sync(0xffffffffu, c2, srcB);
                uint32_t a3b = __shfl_sync(0xffffffffu, c3, srcB);
                uint4 o;
                o.x = odd ? a0b : a0a;
                o.y = odd ? a1b : a1a;
                o.z = odd ? a2b : a2a;
                o.w = odd ? a3b : a3a;
                Qf[((size_t)(headg * 64 + st) * 8 + sub) * 32 + lane] = o;
            } else if (mode == 1) {
                // K -> kc-paired layout: [head][nt(128)][p(4)][lane] uint4,
                // stored as two uint2 halves (q = sub&1) at p = sub>>1.
                uint32_t c0 = f2tf32(v0), c1 = f2tf32(v1);
                uint32_t c2 = f2tf32(v2), c3 = f2tf32(v3);
                uint32_t e0a = __shfl_sync(0xffffffffu, c0, srcA);
                uint32_t e1a = __shfl_sync(0xffffffffu, c1, srcA);
                uint32_t e0b = __shfl_sync(0xffffffffu, c0, srcB);
                uint32_t e1b = __shfl_sync(0xffffffffu, c1, srcB);
                uint32_t f0a = __shfl_sync(0xffffffffu, c2, srcA);
                uint32_t f1a = __shfl_sync(0xffffffffu, c3, srcA);
                uint32_t f0b = __shfl_sync(0xffffffffu, c2, srcB);
                uint32_t f1b = __shfl_sync(0xffffffffu, c3, srcB);
                uint2 fe, fo;
                fe.x = odd ? e1a : e0a;  fe.y = odd ? e1b : e0b;   // keys 0-7  (nt0)
                fo.x = odd ? f1a : f0a;  fo.y = odd ? f1b : f0b;   // keys 8-15 (nt0+1)
                const int nt0 = st * 2;
                const size_t base0 = ((((size_t)headg * 128 + nt0    ) * 4 + (sub >> 1)) * 32 + lane) * 2 + (sub & 1);
                const size_t base1 = ((((size_t)headg * 128 + nt0 + 1) * 4 + (sub >> 1)) * 32 + lane) * 2 + (sub & 1);
                Kf2[base0] = fe;
                Kf2[base1] = fo;
            } else {  // mode 2 : V transpose permute, merged kc-pair uint4 store
                uint32_t c0 = f2tf32(v0), c1 = f2tf32(v1);
                uint32_t c2 = f2tf32(v2), c3 = f2tf32(v3);
                const int src0 = ((lane & 3) << 2) | (lane >> 3);
                const int src1 = src0 + 16;
                const bool sel = (lane >> 2) & 1;
                uint32_t e0 = __shfl_sync(0xffffffffu, c0, src0);
                uint32_t e1 = __shfl_sync(0xffffffffu, c1, src0);
                uint32_t f0 = __shfl_sync(0xffffffffu, c0, src1);
                uint32_t f1 = __shfl_sync(0xffffffffu, c1, src1);
                uint32_t g0 = __shfl_sync(0xffffffffu, c2, src0);
                uint32_t g1 = __shfl_sync(0xffffffffu, c3, src0);
                uint32_t h0 = __shfl_sync(0xffffffffu, c2, src1);
                uint32_t h1 = __shfl_sync(0xffffffffu, c3, src1);
                uint4 o;   // .xy = kc even (keys 0-7), .zw = kc odd (keys 8-15)
                o.x = sel ? e1 : e0;  o.y = sel ? f1 : f0;
                o.z = sel ? g1 : g0;  o.w = sel ? h1 : h0;
                // layout: [head][chunk(16)][p(4)][g(8)][lane] uint4
                const int chunk = st >> 2, p = st & 3;
                Vf4[(((((size_t)headg * 16 + chunk) * 4 + p) * 8 + sub) * 32) + lane] = o;
            }
        }
    }
}

// ---------------------------------------------------------------------------
// Final GEMM (attn-O @ Wo^T + bo -> fp32 out)
// ---------------------------------------------------------------------------
__global__ __launch_bounds__(256, 2)
void gemm_out(const uint4* __restrict__ Af, const uint2* __restrict__ Bf,
              const float* __restrict__ bias, float* __restrict__ C)
{
    const int tid = threadIdx.x, warp = tid >> 5, lane = tid & 31;
    const int wm = warp & 3, wn = warp >> 2;
    const int mt0 = blockIdx.y * 8 + wm * 2;
    const int ntb = blockIdx.x * 16 + wn * 8;

    const uint4* pa0 = Af + (size_t)(mt0 + 0) * KT * 32 + lane;
    const uint4* pa1 = Af + (size_t)(mt0 + 1) * KT * 32 + lane;
    const uint2* pb  = Bf + (size_t)ntb * KT * 32 + lane;

    float acc[2][8][4];
    gemm_mainloop(pa0, pa1, pb, acc);

    const int r = lane >> 2, cq = 2 * (lane & 3);
    #pragma unroll
    for (int t = 0; t < 2; t++) {
        const int row0 = (mt0 + t) * 16 + r, row1 = row0 + 8;
        #pragma unroll
        for (int j = 0; j < 8; j++) {
            const int col = (ntb + j) * 8 + cq;
            float2 bv = *(const float2*)(bias + col);
            *(float2*)&C[(size_t)row0 * EMB + col] = float2{acc[t][j][0] + bv.x, acc[t][j][1] + bv.y};
            *(float2*)&C[(size_t)row1 * EMB + col] = float2{acc[t][j][2] + bv.x, acc[t][j][3] + bv.y};
        }
    }
}

// ---------------------------------------------------------------------------
// Fragment-native tf32 flash attention: 2 m-tiles/warp, 4 warps/CTA,
// cp.async double-buffered smem staging, kc-paired uint4 operand loads
// (32 LDS.128 per matrix per chunk instead of 64 LDS.64).
// ---------------------------------------------------------------------------
__global__ __launch_bounds__(128, 2)
void attn_mma_kernel(const uint4* __restrict__ Qf, const uint4* __restrict__ Kf,
                     const uint4* __restrict__ Vf, uint4* __restrict__ Of)
{
    extern __shared__ uint32_t smf[];   // 2 bufs x (K 16KB + V 16KB) = 64 KB

    const int tid  = threadIdx.x;
    const int warp = tid >> 5;
    const int lane = tid & 31;
    const int head = blockIdx.y;
    const int mt0  = blockIdx.x * 8 + warp * 2;   // two m-tiles per warp

    // ---- Q fragments for both m-tiles: direct coalesced LDG ----
    uint32_t qf[2][8][4];
    #pragma unroll
    for (int m = 0; m < 2; m++)
        #pragma unroll
        for (int kc = 0; kc < 8; kc++)
            *(uint4*)qf[m][kc] = Qf[((size_t)(head * 64 + mt0 + m) * 8 + kc) * 32 + lane];

    const uint32_t smem_base = s2u(smf);
    const char* Kh = (const char*)(Kf + (size_t)head * 128 * 4 * 32);
    const char* Vh = (const char*)(Vf + (size_t)head * 16 * 4 * 8 * 32);

    // stage chunk t into buffer buf (contiguous 16 KB per matrix)
    auto STAGE = [&](int t, int buf) {
        const uint32_t dK = smem_base + buf * 32768 + tid * 16;
        const char* sK = Kh + (size_t)t * 16384 + tid * 16;
        const char* sV = Vh + (size_t)t * 16384 + tid * 16;
        #pragma unroll
        for (int i = 0; i < 8; i++) {
            asm volatile("cp.async.ca.shared.global [%0], [%1], 16;"
                         :: "r"(dK + i * 2048), "l"(sK + (size_t)i * 2048));
            asm volatile("cp.async.ca.shared.global [%0], [%1], 16;"
                         :: "r"(dK + 16384 + i * 2048), "l"(sV + (size_t)i * 2048));
        }
        asm volatile("cp.async.commit_group;" ::: "memory");
    };

    float oacc[2][8][4];
    #pragma unroll
    for (int m = 0; m < 2; m++)
        #pragma unroll
        for (int g = 0; g < 8; g++)
            #pragma unroll
            for (int e = 0; e < 4; e++) oacc[m][g][e] = 0.f;
    float l00 = 0.f, l01 = 0.f, l10 = 0.f, l11 = 0.f;

    const int srcA = (lane & ~3) | ((lane & 3) >> 1);
    const int srcB = srcA | 2;

    STAGE(0, 0);

    for (int t = 0; t < NSEQ / 64; t++) {
        asm volatile("cp.async.wait_group 0;" ::: "memory");
        __syncthreads();
        if (t + 1 < NSEQ / 64) STAGE(t + 1, (t + 1) & 1);
        const uint4* KB4 = (const uint4*)(smf + (t & 1) * 8192);  // [n(8)][p(4)][lane]
        const uint4* VB4 = KB4 + 1024;                            // [p(4)][g(8)][lane]

        // ---- S = Q @ K^T for both m-tiles (kc-paired LDS.128 loads) ----
        float s[2][8][4];
        #pragma unroll
        for (int m = 0; m < 2; m++)
            #pragma unroll
            for (int n = 0; n < 8; n++)
                #pragma unroll
                for (int e = 0; e < 4; e++) s[m][n][e] = 0.f;
        #pragma unroll
        for (int p = 0; p < 4; p++) {
            uint4 kq[8];
            #pragma unroll
            for (int n = 0; n < 8; n++)
                kq[n] = KB4[(n * 4 + p) * 32 + lane];
            #pragma unroll
            for (int n = 0; n < 8; n++) {
                mma_tf32(s[0][n], qf[0][2 * p],     (const uint32_t*)&kq[n].x);
                mma_tf32(s[1][n], qf[1][2 * p],     (const uint32_t*)&kq[n].x);
                mma_tf32(s[0][n], qf[0][2 * p + 1], (const uint32_t*)&kq[n].z);
                mma_tf32(s[1][n], qf[1][2 * p + 1], (const uint32_t*)&kq[n].z);
            }
        }

        // ---- P = 2^S, per-lane l-partials ----
        #pragma unroll
        for (int n = 0; n < 8; n++) {
            s[0][n][0] = ex2f(s[0][n][0]); l00 += s[0][n][0];
            s[0][n][1] = ex2f(s[0][n][1]); l00 += s[0][n][1];
            s[0][n][2] = ex2f(s[0][n][2]); l01 += s[0][n][2];
            s[0][n][3] = ex2f(s[0][n][3]); l01 += s[0][n][3];
            s[1][n][0] = ex2f(s[1][n][0]); l10 += s[1][n][0];
            s[1][n][1] = ex2f(s[1][n][1]); l10 += s[1][n][1];
            s[1][n][2] = ex2f(s[1][n][2]); l11 += s[1][n][2];
            s[1][n][3] = ex2f(s[1][n][3]); l11 += s[1][n][3];
        }

        // ---- P (C-layout) -> A-fragments, in-register lane permute ----
        #pragma unroll
        for (int m = 0; m < 2; m++) {
            #pragma unroll
            for (int n = 0; n < 8; n++) {
                uint32_t c0 = f2tf32(s[m][n][0]), c1 = f2tf32(s[m][n][1]);
                uint32_t c2 = f2tf32(s[m][n][2]), c3 = f2tf32(s[m][n][3]);
                uint32_t a0a = __shfl_sync(0xffffffffu, c0, srcA);
                uint32_t a0b = __shfl_sync(0xffffffffu, c1, srcA);
                uint32_t a1a = __shfl_sync(0xffffffffu, c2, srcA);
                uint32_t a1b = __shfl_sync(0xffffffffu, c3, srcA);
                uint32_t a2a = __shfl_sync(0xffffffffu, c0, srcB);
                uint32_t a2b = __shfl_sync(0xffffffffu, c1, srcB);
                uint32_t a3a = __shfl_sync(0xffffffffu, c2, srcB);
                uint32_t a3b = __shfl_sync(0xffffffffu, c3, srcB);
                const bool odd = (lane & 1);
                s[m][n][0] = __uint_as_float(odd ? a0b : a0a);
                s[m][n][1] = __uint_as_float(odd ? a1b : a1a);
                s[m][n][2] = __uint_as_float(odd ? a2b : a2a);
                s[m][n][3] = __uint_as_float(odd ? a3b : a3a);
            }
        }

        // ---- O += P @ V (kc-paired LDS.128 loads, shared across m-tiles) ----
        #pragma unroll
        for (int p = 0; p < 4; p++) {
            uint4 vq[8];
            #pragma unroll
            for (int g = 0; g < 8; g++)
                vq[g] = VB4[(p * 8 + g) * 32 + lane];
            #pragma unroll
            for (int g = 0; g < 8; g++) {
                mma_tf32(oacc[0][g], (const uint32_t*)s[0][2 * p],     (const uint32_t*)&vq[g].x);
                mma_tf32(oacc[1][g], (const uint32_t*)s[1][2 * p],     (const uint32_t*)&vq[g].x);
                mma_tf32(oacc[0][g], (const uint32_t*)s[0][2 * p + 1], (const uint32_t*)&vq[g].z);
                mma_tf32(oacc[1][g], (const uint32_t*)s[1][2 * p + 1], (const uint32_t*)&vq[g].z);
            }
        }
    }

    // ---- single post-loop l reduction across the 4-lane row group ----
    l00 += __shfl_xor_sync(0xffffffffu, l00, 1);
    l00 += __shfl_xor_sync(0xffffffffu, l00, 2);
    l01 += __shfl_xor_sync(0xffffffffu, l01, 1);
    l01 += __shfl_xor_sync(0xffffffffu, l01, 2);
    l10 += __shfl_xor_sync(0xffffffffu, l10, 1);
    l10 += __shfl_xor_sync(0xffffffffu, l10, 2);
    l11 += __shfl_xor_sync(0xffffffffu, l11, 1);
    l11 += __shfl_xor_sync(0xffffffffu, l11, 2);

    // ---- epilogue: normalize, permute to A-frags, write packed for Wo GEMM ----
    const int b = head / NH, h = head % NH;
    #pragma unroll
    for (int m = 0; m < 2; m++) {
        const float inv0 = 1.0f / (m ? l10 : l00);
        const float inv1 = 1.0f / (m ? l11 : l01);
        const int mt = b * 64 + mt0 + m;
        #pragma unroll
        for (int g = 0; g < 8; g++) {
            uint32_t c0 = f2tf32(oacc[m][g][0] * inv0), c1 = f2tf32(oacc[m][g][1] * inv0);
            uint32_t c2 = f2tf32(oacc[m][g][2] * inv1), c3 = f2tf32(oacc[m][g][3] * inv1);
            uint32_t a0a = __shfl_sync(0xffffffffu, c0, srcA);
            uint32_t a0b = __shfl_sync(0xffffffffu, c1, srcA);
            uint32_t a1a = __shfl_sync(0xffffffffu, c2, srcA);
            uint32_t a1b = __shfl_sync(0xffffffffu, c3, srcA);
            uint32_t a2a = __shfl_sync(0xffffffffu, c0, srcB);
            uint32_t a2b = __shfl_sync(0xffffffffu, c1, srcB);
            uint32_t a3a = __shfl_sync(0xffffffffu, c2, srcB);
            uint32_t a3b = __shfl_sync(0xffffffffu, c3, srcB);
            const bool odd = (lane & 1);
            uint4 o;
            o.x = odd ? a0b : a0a;
            o.y = odd ? a1b : a1a;
            o.z = odd ? a2b : a2a;
            o.w = odd ? a3b : a3a;
            Of[(size_t)(mt * KT + h * 8 + g) * 32 + lane] = o;
        }
    }
}

// ---------------------------------------------------------------------------
extern "C" void kernel_launch(void* const* d_in, const int* in_sizes, int n_in,
                              void* d_out, int out_size)
{
    const float* x  = (const float*)d_in[0];
    const float* Wq = (const float*)d_in[1];
    const float* bq = (const float*)d_in[2];
    const float* Wk = (const float*)d_in[3];
    const float* bk = (const float*)d_in[4];
    const float* Wv = (const float*)d_in[5];
    const float* bv = (const float*)d_in[6];
    const float* Wo = (const float*)d_in[7];
    const float* bo = (const float*)d_in[8];
    float* out = (float*)d_out;

    uint4 *axf, *aof, *qf, *kf4, *vf4;
    uint2 *wf;
    cudaGetSymbolAddress((void**)&axf, g_Axf);
    cudaGetSymbolAddress((void**)&aof, g_Aof);
    cudaGetSymbolAddress((void**)&wf,  g_Wf);
    cudaGetSymbolAddress((void**)&qf,  g_Qf);
    cudaGetSymbolAddress((void**)&kf4, g_Kf4);
    cudaGetSymbolAddress((void**)&vf4, g_Vf4);

    pack_A<<<MT * KT * 32 / 256, 256>>>(x, axf);
    pack_B4<<<dim3(NT * KT * 32 / 256, 4), 256>>>(Wq, Wk, Wv, Wo, wf);

    // fused QKV projections (z = 0:Q, 1:K, 2:V)
    gemm_qkv<<<dim3(EMB / 128, MTOT / 128, 3), 256>>>(axf, wf, bq, bk, bv,
                                                      qf, (uint2*)kf4, vf4);

    const int asmem = 65536;
    cudaFuncSetAttribute(attn_mma_kernel, cudaFuncAttributeMaxDynamicSharedMemorySize, asmem);
    attn_mma_kernel<<<dim3(NSEQ / 128, NHEADS), 128, asmem>>>(qf, kf4, vf4, aof);

    gemm_out<<<dim3(EMB / 128, MTOT / 128), 256>>>(aof, wf + 3 * (size_t)WSZ, bo, out);
}

// round 17
// speedup vs baseline: 1.3377x; 1.3377x over previous
#include <cuda_runtime.h>
#include <cstdint>

#define BSZ  16
#define NSEQ 1024
#define EMB  768
#define NH   12
#define HD   64
#define MTOT (BSZ*NSEQ)   // 16384
#define SCALE 0.125f      // 64^-0.5
#define QSCALE (0.125f * 1.44269504088896340736f)   // SCALE * log2(e)
#define KT   96           // k-chunks of 8 (768/8)
#define MT   1024         // m-tiles of 16 (16384/16)
#define NT   96           // n-tiles of 8 (768/8)
#define WSZ  (NT*KT*32)   // uint2 elements per packed W
#define NHEADS (BSZ*NH)   // 192

// ---------------- scratch (device globals; allocation-free) ----------------
__device__ uint4 g_Axf[MT*KT*32];            // packed x      A-fragments (tf32)
__device__ uint4 g_Aof[MT*KT*32];            // packed attn-O A-fragments (tf32)
__device__ uint2 g_Wf[4][WSZ];               // packed Wq,Wk,Wv,Wo B-fragments
__device__ uint4 g_Qfh[NHEADS*64*4*32];      // Q fp16 A-frags [head][mt(64)][kq(4)][lane]
__device__ uint4 g_Kfh[NHEADS*128*2*32];     // K fp16 B-frags [head][nt(128)][kqp(2)][lane]
__device__ uint4 g_Vfh[NHEADS*16*2*8*32];    // V fp16 B-frags [head][chunk(16)][kqp(2)][g(8)][lane]

// ---------------- helpers ----------------
__device__ __forceinline__ uint32_t f2tf32(float v) {
    uint32_t u;
    asm("cvt.rna.tf32.f32 %0, %1;" : "=r"(u) : "f"(v));
    return u;
}
__device__ __forceinline__ uint32_t h2(float lo, float hi) {   // pack {lo,hi} -> f16x2
    uint32_t r;
    asm("cvt.rn.f16x2.f32 %0, %1, %2;" : "=r"(r) : "f"(hi), "f"(lo));
    return r;
}
__device__ __forceinline__ uint32_t prmt(uint32_t a, uint32_t b, uint32_t sel) {
    uint32_t d;
    asm("prmt.b32 %0, %1, %2, %3;" : "=r"(d) : "r"(a), "r"(b), "r"(sel));
    return d;
}
__device__ __forceinline__ float ex2f(float v) {
    float r;
    asm("ex2.approx.f32 %0, %1;" : "=f"(r) : "f"(v));
    return r;
}
__device__ __forceinline__ uint32_t s2u(const void* p) {
    uint32_t a;
    asm("{ .reg .u64 t; cvta.to.shared.u64 t, %1; cvt.u32.u64 %0, t; }" : "=r"(a) : "l"(p));
    return a;
}
__device__ __forceinline__ void mma_tf32(float* c, const uint32_t* a, const uint32_t* b) {
    asm volatile(
        "mma.sync.aligned.m16n8k8.row.col.f32.tf32.tf32.f32 "
        "{%0,%1,%2,%3}, {%4,%5,%6,%7}, {%8,%9}, {%0,%1,%2,%3};"
        : "+f"(c[0]), "+f"(c[1]), "+f"(c[2]), "+f"(c[3])
        : "r"(a[0]), "r"(a[1]), "r"(a[2]), "r"(a[3]), "r"(b[0]), "r"(b[1]));
}
__device__ __forceinline__ void mma_f16(float* c, const uint32_t* a, const uint32_t* b) {
    asm volatile(
        "mma.sync.aligned.m16n8k16.row.col.f32.f16.f16.f32 "
        "{%0,%1,%2,%3}, {%4,%5,%6,%7}, {%8,%9}, {%0,%1,%2,%3};"
        : "+f"(c[0]), "+f"(c[1]), "+f"(c[2]), "+f"(c[3])
        : "r"(a[0]), "r"(a[1]), "r"(a[2]), "r"(a[3]), "r"(b[0]), "r"(b[1]));
}

// ---------------------------------------------------------------------------
// pack_A ; pack_B4
// ---------------------------------------------------------------------------
__global__ __launch_bounds__(256)
void pack_A(const float* __restrict__ A, uint4* __restrict__ out)
{
    const int t = blockIdx.x * 256 + threadIdx.x;
    const int lane = t & 31, f = t >> 5;
    const int mt = f / KT, kc = f % KT;
    const float* base = A + (size_t)(mt * 16 + (lane >> 2)) * EMB + kc * 8 + (lane & 3);
    uint4 o;
    o.x = f2tf32(base[0]);
    o.y = f2tf32(base[8 * EMB]);
    o.z = f2tf32(base[4]);
    o.w = f2tf32(base[8 * EMB + 4]);
    out[t] = o;
}

__global__ __launch_bounds__(256)
void pack_B4(const float* __restrict__ W0, const float* __restrict__ W1,
             const float* __restrict__ W2, const float* __restrict__ W3,
             uint2* __restrict__ out)
{
    const float* W = (blockIdx.y == 0) ? W0 : (blockIdx.y == 1) ? W1
                   : (blockIdx.y == 2) ? W2 : W3;
    const int t = blockIdx.x * 256 + threadIdx.x;
    const int lane = t & 31, f = t >> 5;
    const int nt = f / KT, kc = f % KT;
    const float* base = W + (size_t)(nt * 8 + (lane >> 2)) * EMB + kc * 8 + (lane & 3);
    uint2 o;
    o.x = f2tf32(base[0]);
    o.y = f2tf32(base[4]);
    out[(size_t)blockIdx.y * WSZ + t] = o;
}

// ---------------------------------------------------------------------------
// tf32 GEMM mainloop (proven; unchanged)
// ---------------------------------------------------------------------------
__device__ __forceinline__ void gemm_mainloop(
    const uint4* __restrict__ pa0, const uint4* __restrict__ pa1,
    const uint2* __restrict__ pb, float acc[2][8][4])
{
    #pragma unroll
    for (int t = 0; t < 2; t++)
        #pragma unroll
        for (int j = 0; j < 8; j++)
            #pragma unroll
            for (int e = 0; e < 4; e++) acc[t][j][e] = 0.f;

    uint4 a0 = pa0[0], a1 = pa1[0];
    uint2 b[8];
    #pragma unroll
    for (int j = 0; j < 8; j++) b[j] = pb[j * KT * 32];

    #pragma unroll 2
    for (int kc = 0; kc < KT; kc++) {
        const uint4 ca0 = a0, ca1 = a1;
        uint2 cb[8];
        #pragma unroll
        for (int j = 0; j < 8; j++) cb[j] = b[j];
        if (kc + 1 < KT) {
            a0 = pa0[(kc + 1) * 32];
            a1 = pa1[(kc + 1) * 32];
            #pragma unroll
            for (int j = 0; j < 8; j++) b[j] = pb[(j * KT + kc + 1) * 32];
        }
        #pragma unroll
        for (int j = 0; j < 8; j++) {
            mma_tf32(acc[0][j], (const uint32_t*)&ca0.x, (const uint32_t*)&cb[j].x);
            mma_tf32(acc[1][j], (const uint32_t*)&ca1.x, (const uint32_t*)&cb[j].x);
        }
    }
}

// ---------------------------------------------------------------------------
// Fused QKV GEMM: fp16 fragment epilogues.
//   mode 0: Q -> fp16 A-frags (QSCALE folded), NO shuffles
//   mode 1: K -> fp16 B-frags (K^T layout ≡ C layout), NO shuffles
//   mode 2: V -> fp16 B-frags (transpose: 4 shfl + 2 prmt per tile)
// ---------------------------------------------------------------------------
__global__ __launch_bounds__(256, 2)
void gemm_qkv(const uint4* __restrict__ Af, const uint2* __restrict__ Wf,
              const float* __restrict__ bq, const float* __restrict__ bk,
              const float* __restrict__ bv,
              uint2* __restrict__ Qh, uint32_t* __restrict__ Kh, uint2* __restrict__ Vh)
{
    const int tid = threadIdx.x, warp = tid >> 5, lane = tid & 31;
    const int wm = warp & 3, wn = warp >> 2;
    const int mt0 = blockIdx.y * 8 + wm * 2;
    const int ntb = blockIdx.x * 16 + wn * 8;
    const int mode = blockIdx.z;

    const uint2* Bf = Wf + (size_t)mode * WSZ;
    const float* bias = (mode == 0) ? bq : (mode == 1) ? bk : bv;

    const uint4* pa0 = Af + (size_t)(mt0 + 0) * KT * 32 + lane;
    const uint4* pa1 = Af + (size_t)(mt0 + 1) * KT * 32 + lane;
    const uint2* pb  = Bf + (size_t)ntb * KT * 32 + lane;

    float acc[2][8][4];
    gemm_mainloop(pa0, pa1, pb, acc);

    const int cq = 2 * (lane & 3);

    #pragma unroll
    for (int t = 0; t < 2; t++) {
        const int mt_g = mt0 + t;
        #pragma unroll
        for (int j = 0; j < 8; j++) {
            const int col = (ntb + j) * 8 + cq;
            float2 bvv = *(const float2*)(bias + col);
            float v0 = acc[t][j][0] + bvv.x, v1 = acc[t][j][1] + bvv.y;
            float v2 = acc[t][j][2] + bvv.x, v3 = acc[t][j][3] + bvv.y;

            const int bb = mt_g >> 6;           // batch
            const int st = mt_g & 63;           // seq tile (16 rows) within batch
            const int col0 = (ntb + j) * 8;
            const int h  = col0 >> 6;           // head 0..11
            const int sub = (col0 & 63) >> 3;   // dim tile 0..7 within head
            const int headg = bb * NH + h;

            if (mode == 0) {
                // Q A-frags: uint4 = (a0,a1,a2,a3); this tile provides half (sub&1)
                uint32_t wlo = h2(v0 * QSCALE, v1 * QSCALE);   // rows r / cols lo
                uint32_t whi = h2(v2 * QSCALE, v3 * QSCALE);   // rows r+8
                const int kq = sub >> 1, half = sub & 1;
                Qh[((((size_t)(headg * 64 + st) * 4 + kq) * 32 + lane) << 1) + half] =
                    make_uint2(wlo, whi);
            } else if (mode == 1) {
                // K B-frags (K^T): b-reg (sub&1), kq = sub>>1; rows0-7 -> nt 2st, rows8-15 -> nt 2st+1
                uint32_t wlo = h2(v0, v1);
                uint32_t whi = h2(v2, v3);
                const int jq = sub >> 1, kqp = jq >> 1, elem = ((jq & 1) << 1) + (sub & 1);
                Kh[((((size_t)(headg * 128 + 2 * st    ) * 2 + kqp) * 32 + lane) << 2) + elem] = wlo;
                Kh[((((size_t)(headg * 128 + 2 * st + 1) * 2 + kqp) * 32 + lane) << 2) + elem] = whi;
            } else {
                // V B-frags: transpose via shfl+prmt
                uint32_t h01 = h2(v0, v1);    // rows r   (keys 0-7 of tile), dims lo/hi
                uint32_t h23 = h2(v2, v3);    // rows r+8 (keys 8-15)
                const int dq = lane >> 2;                   // target dim within tile
                const int s0 = ((lane & 3) << 3) + (dq >> 1);
                const int s1 = s0 + 4;
                uint32_t sh0 = __shfl_sync(0xffffffffu, h01, s0);
                uint32_t sh1 = __shfl_sync(0xffffffffu, h01, s1);
                uint32_t sh2 = __shfl_sync(0xffffffffu, h23, s0);
                uint32_t sh3 = __shfl_sync(0xffffffffu, h23, s1);
                const uint32_t sel = (dq & 1) ? 0x7632u : 0x5410u;
                uint32_t b0 = prmt(sh0, sh1, sel);   // keys 2(l%4),+1
                uint32_t b1 = prmt(sh2, sh3, sel);   // keys +8,+9
                const int chunk = st >> 2, kq = st & 3;
                Vh[((((((size_t)(headg * 16 + chunk) * 2 + (kq >> 1)) * 8 + sub) * 32 + lane) << 1)) + (kq & 1)] =
                    make_uint2(b0, b1);
            }
        }
    }
}

// ---------------------------------------------------------------------------
// Final GEMM (attn-O @ Wo^T + bo -> fp32 out)
// ---------------------------------------------------------------------------
__global__ __launch_bounds__(256, 2)
void gemm_out(const uint4* __restrict__ Af, const uint2* __restrict__ Bf,
              const float* __restrict__ bias, float* __restrict__ C)
{
    const int tid = threadIdx.x, warp = tid >> 5, lane = tid & 31;
    const int wm = warp & 3, wn = warp >> 2;
    const int mt0 = blockIdx.y * 8 + wm * 2;
    const int ntb = blockIdx.x * 16 + wn * 8;

    const uint4* pa0 = Af + (size_t)(mt0 + 0) * KT * 32 + lane;
    const uint4* pa1 = Af + (size_t)(mt0 + 1) * KT * 32 + lane;
    const uint2* pb  = Bf + (size_t)ntb * KT * 32 + lane;

    float acc[2][8][4];
    gemm_mainloop(pa0, pa1, pb, acc);

    const int r = lane >> 2, cq = 2 * (lane & 3);
    #pragma unroll
    for (int t = 0; t < 2; t++) {
        const int row0 = (mt0 + t) * 16 + r, row1 = row0 + 8;
        #pragma unroll
        for (int j = 0; j < 8; j++) {
            const int col = (ntb + j) * 8 + cq;
            float2 bv = *(const float2*)(bias + col);
            *(float2*)&C[(size_t)row0 * EMB + col] = float2{acc[t][j][0] + bv.x, acc[t][j][1] + bv.y};
            *(float2*)&C[(size_t)row1 * EMB + col] = float2{acc[t][j][2] + bv.x, acc[t][j][3] + bv.y};
        }
    }
}

// ---------------------------------------------------------------------------
// fp16 m16n8k16 flash attention: 2 m-tiles/warp, 4 warps/CTA, cp.async
// double-buffered smem (32 KB), shuffle-free P->A conversion (FA2 layout
// identity), fp32 accumulators, chain-free softmax.
// ---------------------------------------------------------------------------
__global__ __launch_bounds__(128, 2)
void attn_mma_kernel(const uint4* __restrict__ Qf, const uint4* __restrict__ Kf,
                     const uint4* __restrict__ Vf, uint4* __restrict__ Of)
{
    extern __shared__ uint32_t smf[];   // 2 bufs x (K 8KB + V 8KB) = 32 KB

    const int tid  = threadIdx.x;
    const int warp = tid >> 5;
    const int lane = tid & 31;
    const int head = blockIdx.y;
    const int mt0  = blockIdx.x * 8 + warp * 2;   // two m-tiles per warp

    // ---- Q fp16 A-fragments for both m-tiles (4 k16-chunks each) ----
    uint32_t qf[2][4][4];
    #pragma unroll
    for (int m = 0; m < 2; m++)
        #pragma unroll
        for (int kq = 0; kq < 4; kq++)
            *(uint4*)qf[m][kq] = Qf[((size_t)(head * 64 + mt0 + m) * 4 + kq) * 32 + lane];

    const uint32_t smem_base = s2u(smf);
    const char* Kh = (const char*)(Kf + (size_t)head * 128 * 2 * 32);
    const char* Vh = (const char*)(Vf + (size_t)head * 16 * 2 * 8 * 32);

    // stage chunk t (8 KB K + 8 KB V) into buffer buf
    auto STAGE = [&](int t, int buf) {
        const uint32_t dK = smem_base + buf * 16384 + tid * 16;
        const char* sK = Kh + (size_t)t * 8192 + tid * 16;
        const char* sV = Vh + (size_t)t * 8192 + tid * 16;
        #pragma unroll
        for (int i = 0; i < 4; i++) {
            asm volatile("cp.async.ca.shared.global [%0], [%1], 16;"
                         :: "r"(dK + i * 2048), "l"(sK + (size_t)i * 2048));
            asm volatile("cp.async.ca.shared.global [%0], [%1], 16;"
                         :: "r"(dK + 8192 + i * 2048), "l"(sV + (size_t)i * 2048));
        }
        asm volatile("cp.async.commit_group;" ::: "memory");
    };

    float oacc[2][8][4];
    #pragma unroll
    for (int m = 0; m < 2; m++)
        #pragma unroll
        for (int g = 0; g < 8; g++)
            #pragma unroll
            for (int e = 0; e < 4; e++) oacc[m][g][e] = 0.f;
    float l00 = 0.f, l01 = 0.f, l10 = 0.f, l11 = 0.f;

    STAGE(0, 0);

    for (int t = 0; t < NSEQ / 64; t++) {
        asm volatile("cp.async.wait_group 0;" ::: "memory");
        __syncthreads();
        if (t + 1 < NSEQ / 64) STAGE(t + 1, (t + 1) & 1);
        const uint4* KB4 = (const uint4*)(smf + (t & 1) * 4096);  // [n(8)][kqp(2)][lane]
        const uint4* VB4 = KB4 + 512;                             // [kqp(2)][g(8)][lane]

        // ---- S = Q @ K^T (fp16 k16 mmas) ----
        float s[2][8][4];
        #pragma unroll
        for (int m = 0; m < 2; m++)
            #pragma unroll
            for (int n = 0; n < 8; n++)
                #pragma unroll
                for (int e = 0; e < 4; e++) s[m][n][e] = 0.f;
        #pragma unroll
        for (int kqp = 0; kqp < 2; kqp++) {
            uint4 kq[8];
            #pragma unroll
            for (int n = 0; n < 8; n++)
                kq[n] = KB4[(n * 2 + kqp) * 32 + lane];
            #pragma unroll
            for (int n = 0; n < 8; n++) {
                mma_f16(s[0][n], qf[0][2 * kqp],     (const uint32_t*)&kq[n].x);
                mma_f16(s[1][n], qf[1][2 * kqp],     (const uint32_t*)&kq[n].x);
                mma_f16(s[0][n], qf[0][2 * kqp + 1], (const uint32_t*)&kq[n].z);
                mma_f16(s[1][n], qf[1][2 * kqp + 1], (const uint32_t*)&kq[n].z);
            }
        }

        // ---- P = 2^S, per-lane l-partials ----
        #pragma unroll
        for (int n = 0; n < 8; n++) {
            s[0][n][0] = ex2f(s[0][n][0]); l00 += s[0][n][0];
            s[0][n][1] = ex2f(s[0][n][1]); l00 += s[0][n][1];
            s[0][n][2] = ex2f(s[0][n][2]); l01 += s[0][n][2];
            s[0][n][3] = ex2f(s[0][n][3]); l01 += s[0][n][3];
            s[1][n][0] = ex2f(s[1][n][0]); l10 += s[1][n][0];
            s[1][n][1] = ex2f(s[1][n][1]); l10 += s[1][n][1];
            s[1][n][2] = ex2f(s[1][n][2]); l11 += s[1][n][2];
            s[1][n][3] = ex2f(s[1][n][3]); l11 += s[1][n][3];
        }

        // ---- P (fp32 C-layout) -> fp16 A-frags: pure packing, NO shuffles ----
        uint32_t pa[2][4][4];
        #pragma unroll
        for (int m = 0; m < 2; m++)
            #pragma unroll
            for (int kq = 0; kq < 4; kq++) {
                pa[m][kq][0] = h2(s[m][2 * kq][0],     s[m][2 * kq][1]);
                pa[m][kq][1] = h2(s[m][2 * kq][2],     s[m][2 * kq][3]);
                pa[m][kq][2] = h2(s[m][2 * kq + 1][0], s[m][2 * kq + 1][1]);
                pa[m][kq][3] = h2(s[m][2 * kq + 1][2], s[m][2 * kq + 1][3]);
            }

        // ---- O += P @ V (fp16 k16 mmas) ----
        #pragma unroll
        for (int kqp = 0; kqp < 2; kqp++) {
            uint4 vq[8];
            #pragma unroll
            for (int g = 0; g < 8; g++)
                vq[g] = VB4[(kqp * 8 + g) * 32 + lane];
            #pragma unroll
            for (int g = 0; g < 8; g++) {
                mma_f16(oacc[0][g], pa[0][2 * kqp],     (const uint32_t*)&vq[g].x);
                mma_f16(oacc[1][g], pa[1][2 * kqp],     (const uint32_t*)&vq[g].x);
                mma_f16(oacc[0][g], pa[0][2 * kqp + 1], (const uint32_t*)&vq[g].z);
                mma_f16(oacc[1][g], pa[1][2 * kqp + 1], (const uint32_t*)&vq[g].z);
            }
        }
    }

    // ---- single post-loop l reduction ----
    l00 += __shfl_xor_sync(0xffffffffu, l00, 1);
    l00 += __shfl_xor_sync(0xffffffffu, l00, 2);
    l01 += __shfl_xor_sync(0xffffffffu, l01, 1);
    l01 += __shfl_xor_sync(0xffffffffu, l01, 2);
    l10 += __shfl_xor_sync(0xffffffffu, l10, 1);
    l10 += __shfl_xor_sync(0xffffffffu, l10, 2);
    l11 += __shfl_xor_sync(0xffffffffu, l11, 1);
    l11 += __shfl_xor_sync(0xffffffffu, l11, 2);

    // ---- epilogue: normalize, permute to tf32 A-frags for Wo GEMM ----
    const int b = head / NH, h = head % NH;
    const int srcA = (lane & ~3) | ((lane & 3) >> 1);
    const int srcB = srcA | 2;
    #pragma unroll
    for (int m = 0; m < 2; m++) {
        const float inv0 = 1.0f / (m ? l10 : l00);
        const float inv1 = 1.0f / (m ? l11 : l01);
        const int mt = b * 64 + mt0 + m;
        #pragma unroll
        for (int g = 0; g < 8; g++) {
            uint32_t c0 = f2tf32(oacc[m][g][0] * inv0), c1 = f2tf32(oacc[m][g][1] * inv0);
            uint32_t c2 = f2tf32(oacc[m][g][2] * inv1), c3 = f2tf32(oacc[m][g][3] * inv1);
            uint32_t a0a = __shfl_sync(0xffffffffu, c0, srcA);
            uint32_t a0b = __shfl_sync(0xffffffffu, c1, srcA);
            uint32_t a1a = __shfl_sync(0xffffffffu, c2, srcA);
            uint32_t a1b = __shfl_sync(0xffffffffu, c3, srcA);
            uint32_t a2a = __shfl_sync(0xffffffffu, c0, srcB);
            uint32_t a2b = __shfl_sync(0xffffffffu, c1, srcB);
            uint32_t a3a = __shfl_sync(0xffffffffu, c2, srcB);
            uint32_t a3b = __shfl_sync(0xffffffffu, c3, srcB);
            const bool odd = (lane & 1);
            uint4 o;
            o.x = odd ? a0b : a0a;
            o.y = odd ? a1b : a1a;
            o.z = odd ? a2b : a2a;
            o.w = odd ? a3b : a3a;
            Of[(size_t)(mt * KT + h * 8 + g) * 32 + lane] = o;
        }
    }
}

// ---------------------------------------------------------------------------
extern "C" void kernel_launch(void* const* d_in, const int* in_sizes, int n_in,
                              void* d_out, int out_size)
{
    const float* x  = (const float*)d_in[0];
    const float* Wq = (const float*)d_in[1];
    const float* bq = (const float*)d_in[2];
    const float* Wk = (const float*)d_in[3];
    const float* bk = (const float*)d_in[4];
    const float* Wv = (const float*)d_in[5];
    const float* bv = (const float*)d_in[6];
    const float* Wo = (const float*)d_in[7];
    const float* bo = (const float*)d_in[8];
    float* out = (float*)d_out;

    uint4 *axf, *aof, *qfh, *kfh, *vfh;
    uint2 *wf;
    cudaGetSymbolAddress((void**)&axf, g_Axf);
    cudaGetSymbolAddress((void**)&aof, g_Aof);
    cudaGetSymbolAddress((void**)&wf,  g_Wf);
    cudaGetSymbolAddress((void**)&qfh, g_Qfh);
    cudaGetSymbolAddress((void**)&kfh, g_Kfh);
    cudaGetSymbolAddress((void**)&vfh, g_Vfh);

    pack_A<<<MT * KT * 32 / 256, 256>>>(x, axf);
    pack_B4<<<dim3(NT * KT * 32 / 256, 4), 256>>>(Wq, Wk, Wv, Wo, wf);

    // fused QKV projections (z = 0:Q, 1:K, 2:V) with fp16 fragment epilogues
    gemm_qkv<<<dim3(EMB / 128, MTOT / 128, 3), 256>>>(axf, wf, bq, bk, bv,
                                                      (uint2*)qfh, (uint32_t*)kfh, (uint2*)vfh);

    const int asmem = 32768;
    cudaFuncSetAttribute(attn_mma_kernel, cudaFuncAttributeMaxDynamicSharedMemorySize, asmem);
    attn_mma_kernel<<<dim3(NSEQ / 128, NHEADS), 128, asmem>>>(qfh, kfh, vfh, aof);

    gemm_out<<<dim3(EMB / 128, MTOT / 128), 256>>>(aof, wf + 3 * (size_t)WSZ, bo, out);
}